// round 16
// baseline (speedup 1.0000x reference)
#include <cuda_runtime.h>
#include <cuda_bf16.h>
#include <math.h>
#include <stdint.h>

// Problem dims
#define B_   4
#define T_   2048
#define D_   1024
#define H_   16
#define HD_  64
#define BT_  (B_*T_)          // 8192 rows

typedef __nv_bfloat16 bf16;

// ---------------- scratch (device globals: no runtime allocation) ----------
__device__ bf16 g_xnh[BT_*D_];     // layernorm output bf16   [BT, D]
__device__ bf16 g_wqT[3*D_*D_];    // w_qkv transposed bf16   [3D, D] (n-major, k contiguous)
__device__ bf16 g_wpT[D_*D_];      // w_proj transposed bf16  [D, D]
__device__ bf16 g_q [BT_*D_];      // Q bf16 [B,H,T,HD]
__device__ bf16 g_k [BT_*D_];      // K bf16 [B,H,T,HD]
__device__ bf16 g_v [BT_*D_];      // V bf16 [B,H,T,HD]
__device__ bf16 g_aoh[BT_*D_];     // attention out bf16 [B,T,D]

// ---------------- helpers ---------------------------------------------------
__device__ __forceinline__ uint32_t pack_bf16(float lo, float hi) {
    uint32_t r;
    asm("cvt.rn.bf16x2.f32 %0, %1, %2;" : "=r"(r) : "f"(hi), "f"(lo));
    return r;
}
__device__ __forceinline__ void mma_bf16(float* c, const uint32_t* a, const uint32_t* b) {
    asm volatile(
        "mma.sync.aligned.m16n8k16.row.col.f32.bf16.bf16.f32 "
        "{%0,%1,%2,%3}, {%4,%5,%6,%7}, {%8,%9}, {%0,%1,%2,%3};\n"
        : "+f"(c[0]), "+f"(c[1]), "+f"(c[2]), "+f"(c[3])
        : "r"(a[0]), "r"(a[1]), "r"(a[2]), "r"(a[3]), "r"(b[0]), "r"(b[1]));
}
__device__ __forceinline__ void ldsm_x4(uint32_t* r, uint32_t addr) {
    asm volatile("ldmatrix.sync.aligned.m8n8.x4.shared.b16 {%0,%1,%2,%3}, [%4];"
        : "=r"(r[0]), "=r"(r[1]), "=r"(r[2]), "=r"(r[3]) : "r"(addr));
}
__device__ __forceinline__ void ldsm_x4t(uint32_t* r, uint32_t addr) {
    asm volatile("ldmatrix.sync.aligned.m8n8.x4.trans.shared.b16 {%0,%1,%2,%3}, [%4];"
        : "=r"(r[0]), "=r"(r[1]), "=r"(r[2]), "=r"(r[3]) : "r"(addr));
}
__device__ __forceinline__ void cpa16(uint32_t s, const void* g) {
    asm volatile("cp.async.cg.shared.global [%0], [%1], 16;\n" :: "r"(s), "l"(g));
}
#define CP_COMMIT() asm volatile("cp.async.commit_group;")

// ======================= weight transpose + bf16 convert ===================
__global__ void wtrans_qkv(const float* __restrict__ src) {   // [1024][3072]
    __shared__ float t[32][33];
    int c0 = blockIdx.x * 32, r0 = blockIdx.y * 32;
    int x = threadIdx.x, y = threadIdx.y;
    #pragma unroll
    for (int j = 0; j < 32; j += 8)
        t[y+j][x] = src[(size_t)(r0+y+j) * 3072 + c0 + x];
    __syncthreads();
    #pragma unroll
    for (int j = 0; j < 32; j += 8)
        g_wqT[(size_t)(c0+y+j) * 1024 + r0 + x] = __float2bfloat16(t[x][y+j]);
}
__global__ void wtrans_proj(const float* __restrict__ src) {  // [1024][1024]
    __shared__ float t[32][33];
    int c0 = blockIdx.x * 32, r0 = blockIdx.y * 32;
    int x = threadIdx.x, y = threadIdx.y;
    #pragma unroll
    for (int j = 0; j < 32; j += 8)
        t[y+j][x] = src[(size_t)(r0+y+j) * 1024 + c0 + x];
    __syncthreads();
    #pragma unroll
    for (int j = 0; j < 32; j += 8)
        g_wpT[(size_t)(c0+y+j) * 1024 + r0 + x] = __float2bfloat16(t[x][y+j]);
}

// ======================= LayerNorm (bf16 out) ==============================
__global__ void ln_kernel(const float* __restrict__ x,
                          const float* __restrict__ gamma,
                          const float* __restrict__ beta) {
    int row = blockIdx.x;
    int tid = threadIdx.x;
    const float4* xr = reinterpret_cast<const float4*>(x + (size_t)row * D_);
    float4 v = xr[tid];
    float s  = v.x + v.y + v.z + v.w;
    float sq = v.x*v.x + v.y*v.y + v.z*v.z + v.w*v.w;
    #pragma unroll
    for (int o = 16; o > 0; o >>= 1) {
        s  += __shfl_xor_sync(0xffffffffu, s,  o);
        sq += __shfl_xor_sync(0xffffffffu, sq, o);
    }
    __shared__ float ss[8], sq2[8];
    __shared__ float mu_s, rs_s;
    if ((tid & 31) == 0) { ss[tid >> 5] = s; sq2[tid >> 5] = sq; }
    __syncthreads();
    if (tid == 0) {
        float a = 0.f, b2 = 0.f;
        #pragma unroll
        for (int i = 0; i < 8; i++) { a += ss[i]; b2 += sq2[i]; }
        float mu  = a * (1.0f / D_);
        float var = b2 * (1.0f / D_) - mu * mu;
        mu_s = mu;
        rs_s = rsqrtf(var + 1e-5f);
    }
    __syncthreads();
    float mu = mu_s, rs = rs_s;
    float4 g  = reinterpret_cast<const float4*>(gamma)[tid];
    float4 be = reinterpret_cast<const float4*>(beta)[tid];
    float o0 = (v.x - mu) * rs * g.x + be.x;
    float o1 = (v.y - mu) * rs * g.y + be.y;
    float o2 = (v.z - mu) * rs * g.z + be.z;
    float o3 = (v.w - mu) * rs * g.w + be.w;
    uint2 packed = make_uint2(pack_bf16(o0, o1), pack_bf16(o2, o3));
    *reinterpret_cast<uint2*>(g_xnh + (size_t)row * D_ + tid * 4) = packed;
}

// ======= bf16 GEMM core: period double-buffer, K=64 per barrier ============
// A: [M][1024] bf16 row-major. B: [N][1024] bf16 (n-major, k contiguous).
// 4 slots of 20480 B (A 128x80B + B 128x80B) grouped as two 40960 B halves.
// Period = 2 k-blocks (K=64): ONE wait_group 0 + ONE __syncthreads, then
// prefetch next period (one commit group) and run 4 k16 chunks of mma.
// 16 barriers total (was 32). Write-after-read: half (p+1)&1 was consumed in
// period p-1, proven done by period p's barrier.
#define GEMM_SMEM 81920

__device__ __forceinline__ void gemm_core_p2(
    const bf16* __restrict__ Agm, const bf16* __restrict__ Bgm,
    int m0, int n0, float acc[4][4][4])
{
    extern __shared__ uint32_t smem_u[];
    uint32_t smb = (uint32_t)__cvta_generic_to_shared(smem_u);
    int tid = threadIdx.x, lane = tid & 31, wid = tid >> 5;
    int warp_m = (wid & 1) * 64, warp_n = (wid >> 1) * 32;

    int row = tid & 127, mat = tid >> 7;           // 0 = A row, 1 = B row
    const bf16* gp = mat ? (Bgm + (size_t)(n0 + row) * D_)
                         : (Agm + (size_t)(m0 + row) * D_);
    uint32_t sbase = smb + mat * 10240 + row * 80;

    // preload period 0 (k-blocks 0,1) into half 0
    #pragma unroll
    for (int kb = 0; kb < 2; kb++)
        #pragma unroll
        for (int j = 0; j < 4; j++)
            cpa16(sbase + kb * 20480 + j * 16, gp + kb * 32 + j * 8);
    CP_COMMIT();

    uint32_t a_lane = smb + (warp_m + (lane & 15)) * 80 + ((lane >> 4) << 4);
    uint32_t b_lane = smb + 10240 + (warp_n + (lane & 7)) * 80 +
                      (((lane >> 3) & 1) << 4) + (lane >> 4) * 640;

    #pragma unroll 2
    for (int p = 0; p < 16; p++) {
        asm volatile("cp.async.wait_group 0;");
        __syncthreads();   // period p data visible; period p-1 reads done

        if (p < 15) {      // prefetch period p+1 into the other half
            uint32_t hb = ((p + 1) & 1) * 40960;
            const bf16* g2 = gp + (size_t)(2 * (p + 1)) * 32;
            #pragma unroll
            for (int kb = 0; kb < 2; kb++)
                #pragma unroll
                for (int j = 0; j < 4; j++)
                    cpa16(sbase + hb + kb * 20480 + j * 16, g2 + kb * 32 + j * 8);
            CP_COMMIT();
        }

        uint32_t hoff = (p & 1) * 40960;
        #pragma unroll
        for (int kb = 0; kb < 2; kb++) {
            uint32_t ab = a_lane + hoff + kb * 20480;
            uint32_t bb = b_lane + hoff + kb * 20480;
            #pragma unroll
            for (int c = 0; c < 2; c++) {          // 2 chunks of k16
                uint32_t af[4][4], bfr[2][4];
                #pragma unroll
                for (int mt = 0; mt < 4; mt++) ldsm_x4(af[mt], ab + mt * 1280 + c * 32);
                #pragma unroll
                for (int np = 0; np < 2; np++) ldsm_x4(bfr[np], bb + np * 1280 + c * 32);
                #pragma unroll
                for (int mt = 0; mt < 4; mt++)
                    #pragma unroll
                    for (int np = 0; np < 2; np++) {
                        mma_bf16(acc[mt][2*np],     af[mt], bfr[np]);
                        mma_bf16(acc[mt][2*np + 1], af[mt], bfr[np] + 2);
                    }
            }
        }
    }
    __syncthreads();
}

// ======================= QKV GEMM ==========================================
__global__ __launch_bounds__(256, 2) void qkv_gemm(const float* __restrict__ bias) {
    float acc[4][4][4] = {};
    int m0 = blockIdx.y * 128, n0 = blockIdx.x * 128;
    gemm_core_p2(g_xnh, g_wqT, m0, n0, acc);

    int lane = threadIdx.x & 31, wid = threadIdx.x >> 5;
    int warp_m = (wid & 1) * 64, warp_n = (wid >> 1) * 32;
    #pragma unroll
    for (int mt = 0; mt < 4; mt++) {
        #pragma unroll
        for (int half = 0; half < 2; half++) {
            int bt = m0 + warp_m + mt * 16 + (lane >> 2) + half * 8;
            int bb = bt >> 11;
            int t  = bt & 2047;
            #pragma unroll
            for (int nt = 0; nt < 4; nt++) {
                int c = n0 + warp_n + nt * 8 + (lane & 3) * 2;
                float v0 = acc[mt][nt][half*2+0] + bias[c];
                float v1 = acc[mt][nt][half*2+1] + bias[c+1];
                int s   = c >> 10;
                int rem = c & 1023;
                int hh  = rem >> 6;
                int d   = rem & 63;
                bf16* dst = (s == 0) ? g_q : ((s == 1) ? g_k : g_v);
                *reinterpret_cast<uint32_t*>(
                    &dst[((size_t)((bb * H_ + hh) * T_) + t) * HD_ + d]) =
                    pack_bf16(v0, v1);
            }
        }
    }
}

// ======================= Proj GEMM + bias + residual =======================
__global__ __launch_bounds__(256, 2) void proj_gemm(const float* __restrict__ bias,
                                                    const float* __restrict__ xres,
                                                    float* __restrict__ out) {
    float acc[4][4][4] = {};
    int m0 = blockIdx.y * 128, n0 = blockIdx.x * 128;
    gemm_core_p2(g_aoh, g_wpT, m0, n0, acc);

    int lane = threadIdx.x & 31, wid = threadIdx.x >> 5;
    int warp_m = (wid & 1) * 64, warp_n = (wid >> 1) * 32;
    #pragma unroll
    for (int mt = 0; mt < 4; mt++) {
        #pragma unroll
        for (int half = 0; half < 2; half++) {
            int row = m0 + warp_m + mt * 16 + (lane >> 2) + half * 8;
            #pragma unroll
            for (int nt = 0; nt < 4; nt++) {
                int c = n0 + warp_n + nt * 8 + (lane & 3) * 2;
                float2 bi = *reinterpret_cast<const float2*>(&bias[c]);
                float2 xr = *reinterpret_cast<const float2*>(&xres[(size_t)row * D_ + c]);
                float2 o;
                o.x = acc[mt][nt][half*2+0] + bi.x + xr.x;
                o.y = acc[mt][nt][half*2+1] + bi.y + xr.y;
                *reinterpret_cast<float2*>(&out[(size_t)row * D_ + c]) = o;
            }
        }
    }
}

// ======================= Flash Attention v2 (register softmax) =============
// 3-stage KV ring, ONE barrier per tile (was two). Stage (kt+2)%3 is written
// at iter kt; it was last read at kt-1, proven done by kt's start barrier.
// smem: Q [0,18432) ; K[3] [18432,46080) ; V[3] [46080,73728)
#define ATTN_SMEM 73728

__global__ __launch_bounds__(256, 2) void attn_kernel() {
    extern __shared__ char smraw[];
    uint32_t smem_b = (uint32_t)__cvta_generic_to_shared(smraw);
    const uint32_t K_BASE = 18432, V_BASE = 46080, KV_STG = 9216;

    int tid  = threadIdx.x;
    int lane = tid & 31, wid = tid >> 5;
    int warp_m = wid * 16;
    int g = lane >> 2;

    int qtile = blockIdx.x, h = blockIdx.y, b = blockIdx.z;
    size_t bh = (size_t)(b * H_ + h) * T_ * HD_;
    const bf16* Qg  = g_q + bh + (size_t)qtile * 128 * HD_;
    const bf16* Kg0 = g_k + bh;
    const bf16* Vg0 = g_v + bh;

    int kr = tid >> 2, kp = tid & 3;
    // G0: Q + K0 + V0
    {
        int qr = tid >> 1, qh = tid & 1;
        uint32_t dq = smem_b + qr * 144 + qh * 64;
        const bf16* sq = Qg + qr * 64 + qh * 32;
        cpa16(dq, sq); cpa16(dq + 16, sq + 8);
        cpa16(dq + 32, sq + 16); cpa16(dq + 48, sq + 24);
        uint32_t dk = smem_b + K_BASE + kr * 144 + kp * 32;
        uint32_t dv = smem_b + V_BASE + kr * 144 + kp * 32;
        const bf16* sk = Kg0 + kr * 64 + kp * 16;
        const bf16* sv = Vg0 + kr * 64 + kp * 16;
        cpa16(dk, sk); cpa16(dk + 16, sk + 8);
        cpa16(dv, sv); cpa16(dv + 16, sv + 8);
    }
    CP_COMMIT();
    // G1: K1 + V1 into stage 1
    {
        uint32_t dk = smem_b + K_BASE + KV_STG + kr * 144 + kp * 32;
        uint32_t dv = smem_b + V_BASE + KV_STG + kr * 144 + kp * 32;
        const bf16* sk = Kg0 + (size_t)64 * HD_ + kr * 64 + kp * 16;
        const bf16* sv = Vg0 + (size_t)64 * HD_ + kr * 64 + kp * 16;
        cpa16(dk, sk); cpa16(dk + 16, sk + 8);
        cpa16(dv, sv); cpa16(dv + 16, sv + 8);
    }
    CP_COMMIT();

    uint32_t q_lane = smem_b + (warp_m + (lane & 15)) * 144 + ((lane >> 4) << 4);
    uint32_t k_lane = smem_b + K_BASE + (lane & 7) * 144 +
                      (((lane >> 3) & 1) << 4) + (lane >> 4) * 1152;
    uint32_t v_lane = smem_b + V_BASE + (lane & 15) * 144 + (lane >> 4) * 16;

    float O[8][4] = {};
    float m0r = -1e30f, m1r = -1e30f;
    float l0 = 0.f, l1 = 0.f;

    for (int kt = 0; kt < 32; kt++) {
        if (kt < 31) asm volatile("cp.async.wait_group 1;");
        else         asm volatile("cp.async.wait_group 0;");
        __syncthreads();   // stage kt%3 visible; stage (kt+2)%3 reads (iter kt-1) done

        if (kt < 30) {     // prefetch tile kt+2 into stage (kt+2)%3
            uint32_t st = (uint32_t)((kt + 2) % 3) * KV_STG;
            const bf16* sk = Kg0 + (size_t)(kt + 2) * 64 * HD_ + kr * 64 + kp * 16;
            const bf16* sv = Vg0 + (size_t)(kt + 2) * 64 * HD_ + kr * 64 + kp * 16;
            uint32_t dk = smem_b + K_BASE + st + kr * 144 + kp * 32;
            uint32_t dv = smem_b + V_BASE + st + kr * 144 + kp * 32;
            cpa16(dk, sk); cpa16(dk + 16, sk + 8);
            cpa16(dv, sv); cpa16(dv + 16, sv + 8);
            CP_COMMIT();
        }

        uint32_t soff = (uint32_t)(kt % 3) * KV_STG;
        uint32_t kb = k_lane + soff;
        uint32_t vb = v_lane + soff;

        // ---- S = Q K^T : 16 rows x 64 keys --------------------------------
        float sacc[8][4] = {};
        #pragma unroll
        for (int c = 0; c < 4; c++) {
            uint32_t qf[4];
            ldsm_x4(qf, q_lane + c * 32);
            #pragma unroll
            for (int np = 0; np < 4; np++) {
                uint32_t kf[4];
                ldsm_x4(kf, kb + np * 2304 + c * 32);
                mma_bf16(sacc[2*np],     qf, kf);
                mma_bf16(sacc[2*np + 1], qf, kf + 2);
            }
        }

        // ---- register softmax (rows g and g+8) ----------------------------
        const float scale = 0.125f;
        float mx0 = -1e30f, mx1 = -1e30f;
        #pragma unroll
        for (int nt = 0; nt < 8; nt++) {
            sacc[nt][0] *= scale; sacc[nt][1] *= scale;
            sacc[nt][2] *= scale; sacc[nt][3] *= scale;
            mx0 = fmaxf(mx0, fmaxf(sacc[nt][0], sacc[nt][1]));
            mx1 = fmaxf(mx1, fmaxf(sacc[nt][2], sacc[nt][3]));
        }
        mx0 = fmaxf(mx0, __shfl_xor_sync(0xffffffffu, mx0, 1));
        mx0 = fmaxf(mx0, __shfl_xor_sync(0xffffffffu, mx0, 2));
        mx1 = fmaxf(mx1, __shfl_xor_sync(0xffffffffu, mx1, 1));
        mx1 = fmaxf(mx1, __shfl_xor_sync(0xffffffffu, mx1, 2));
        float mn0 = fmaxf(m0r, mx0), mn1 = fmaxf(m1r, mx1);
        float al0 = __expf(m0r - mn0), al1 = __expf(m1r - mn1);
        float s0 = 0.f, s1 = 0.f;
        uint32_t pf[4][4];
        #pragma unroll
        for (int np = 0; np < 4; np++) {
            float p00 = __expf(sacc[2*np][0]   - mn0), p01 = __expf(sacc[2*np][1]   - mn0);
            float p10 = __expf(sacc[2*np][2]   - mn1), p11 = __expf(sacc[2*np][3]   - mn1);
            float p02 = __expf(sacc[2*np+1][0] - mn0), p03 = __expf(sacc[2*np+1][1] - mn0);
            float p12 = __expf(sacc[2*np+1][2] - mn1), p13 = __expf(sacc[2*np+1][3] - mn1);
            s0 += (p00 + p01) + (p02 + p03);
            s1 += (p10 + p11) + (p12 + p13);
            pf[np][0] = pack_bf16(p00, p01);
            pf[np][1] = pack_bf16(p10, p11);
            pf[np][2] = pack_bf16(p02, p03);
            pf[np][3] = pack_bf16(p12, p13);
        }
        s0 += __shfl_xor_sync(0xffffffffu, s0, 1);
        s0 += __shfl_xor_sync(0xffffffffu, s0, 2);
        s1 += __shfl_xor_sync(0xffffffffu, s1, 1);
        s1 += __shfl_xor_sync(0xffffffffu, s1, 2);
        l0 = l0 * al0 + s0;
        l1 = l1 * al1 + s1;
        m0r = mn0; m1r = mn1;

        // ---- O = O*alpha + P V -------------------------------------------
        #pragma unroll
        for (int nt = 0; nt < 8; nt++) {
            O[nt][0] *= al0; O[nt][1] *= al0;
            O[nt][2] *= al1; O[nt][3] *= al1;
        }
        #pragma unroll
        for (int kc = 0; kc < 4; kc++) {
            #pragma unroll
            for (int np = 0; np < 4; np++) {
                uint32_t vf[4];
                ldsm_x4t(vf, vb + kc * 2304 + np * 32);
                mma_bf16(O[2*np],     pf[kc], vf);
                mma_bf16(O[2*np + 1], pf[kc], vf + 2);
            }
        }
        // no end-of-body barrier: next iteration's start barrier protects reuse
    }

    float li0 = 1.f / l0, li1 = 1.f / l1;
    size_t outbase = ((size_t)b * T_ + qtile * 128 + warp_m) * D_ + h * HD_;
    int t2 = (lane & 3) * 2;
    #pragma unroll
    for (int nt = 0; nt < 8; nt++) {
        int c = nt * 8 + t2;
        *reinterpret_cast<uint32_t*>(&g_aoh[outbase + (size_t)g * D_ + c]) =
            pack_bf16(O[nt][0] * li0, O[nt][1] * li0);
        *reinterpret_cast<uint32_t*>(&g_aoh[outbase + (size_t)(g + 8) * D_ + c]) =
            pack_bf16(O[nt][2] * li1, O[nt][3] * li1);
    }
}

// ======================= launch ============================================
extern "C" void kernel_launch(void* const* d_in, const int* in_sizes, int n_in,
                              void* d_out, int out_size) {
    const float* x      = (const float*)d_in[0];
    const float* w_qkv  = (const float*)d_in[1];
    const float* b_qkv  = (const float*)d_in[2];
    const float* w_proj = (const float*)d_in[3];
    const float* b_proj = (const float*)d_in[4];
    const float* gamma  = (const float*)d_in[5];
    const float* beta   = (const float*)d_in[6];
    float* out = (float*)d_out;

    cudaFuncSetAttribute(attn_kernel,
                         cudaFuncAttributeMaxDynamicSharedMemorySize, ATTN_SMEM);
    cudaFuncSetAttribute(qkv_gemm,
                         cudaFuncAttributeMaxDynamicSharedMemorySize, GEMM_SMEM);
    cudaFuncSetAttribute(proj_gemm,
                         cudaFuncAttributeMaxDynamicSharedMemorySize, GEMM_SMEM);

    wtrans_qkv<<<dim3(96, 32), dim3(32, 8)>>>(w_qkv);
    wtrans_proj<<<dim3(32, 32), dim3(32, 8)>>>(w_proj);
    ln_kernel<<<BT_, 256>>>(x, gamma, beta);
    qkv_gemm<<<dim3(24, 64), 256, GEMM_SMEM>>>(b_qkv);
    attn_kernel<<<dim3(T_ / 128, H_, B_), 256, ATTN_SMEM>>>();
    proj_gemm<<<dim3(8, 64), 256, GEMM_SMEM>>>(b_proj, x, out);
}

// round 17
// speedup vs baseline: 1.1189x; 1.1189x over previous
#include <cuda_runtime.h>
#include <cuda_bf16.h>
#include <math.h>
#include <stdint.h>

// Problem dims
#define B_   4
#define T_   2048
#define D_   1024
#define H_   16
#define HD_  64
#define BT_  (B_*T_)          // 8192 rows

typedef __nv_bfloat16 bf16;

// ---------------- scratch (device globals: no runtime allocation) ----------
__device__ bf16 g_xnh[BT_*D_];     // layernorm output bf16   [BT, D]
__device__ bf16 g_wqT[3*D_*D_];    // w_qkv transposed bf16   [3D, D] (n-major, k contiguous)
__device__ bf16 g_wpT[D_*D_];      // w_proj transposed bf16  [D, D]
__device__ bf16 g_q [BT_*D_];      // Q bf16 [B,H,T,HD]
__device__ bf16 g_k [BT_*D_];      // K bf16 [B,H,T,HD]
__device__ bf16 g_v [BT_*D_];      // V bf16 [B,H,T,HD]
__device__ bf16 g_aoh[BT_*D_];     // attention out bf16 [B,T,D]

// ---------------- helpers ---------------------------------------------------
__device__ __forceinline__ uint32_t pack_bf16(float lo, float hi) {
    uint32_t r;
    asm("cvt.rn.bf16x2.f32 %0, %1, %2;" : "=r"(r) : "f"(hi), "f"(lo));
    return r;
}
__device__ __forceinline__ void mma_bf16(float* c, const uint32_t* a, const uint32_t* b) {
    asm volatile(
        "mma.sync.aligned.m16n8k16.row.col.f32.bf16.bf16.f32 "
        "{%0,%1,%2,%3}, {%4,%5,%6,%7}, {%8,%9}, {%0,%1,%2,%3};\n"
        : "+f"(c[0]), "+f"(c[1]), "+f"(c[2]), "+f"(c[3])
        : "r"(a[0]), "r"(a[1]), "r"(a[2]), "r"(a[3]), "r"(b[0]), "r"(b[1]));
}
__device__ __forceinline__ void ldsm_x4(uint32_t* r, uint32_t addr) {
    asm volatile("ldmatrix.sync.aligned.m8n8.x4.shared.b16 {%0,%1,%2,%3}, [%4];"
        : "=r"(r[0]), "=r"(r[1]), "=r"(r[2]), "=r"(r[3]) : "r"(addr));
}
__device__ __forceinline__ void ldsm_x4t(uint32_t* r, uint32_t addr) {
    asm volatile("ldmatrix.sync.aligned.m8n8.x4.trans.shared.b16 {%0,%1,%2,%3}, [%4];"
        : "=r"(r[0]), "=r"(r[1]), "=r"(r[2]), "=r"(r[3]) : "r"(addr));
}
__device__ __forceinline__ void cpa16(uint32_t s, const void* g) {
    asm volatile("cp.async.cg.shared.global [%0], [%1], 16;\n" :: "r"(s), "l"(g));
}
#define CP_COMMIT() asm volatile("cp.async.commit_group;")

// ======================= weight transpose + bf16 convert ===================
__global__ void wtrans_qkv(const float* __restrict__ src) {   // [1024][3072]
    __shared__ float t[32][33];
    int c0 = blockIdx.x * 32, r0 = blockIdx.y * 32;
    int x = threadIdx.x, y = threadIdx.y;
    #pragma unroll
    for (int j = 0; j < 32; j += 8)
        t[y+j][x] = src[(size_t)(r0+y+j) * 3072 + c0 + x];
    __syncthreads();
    #pragma unroll
    for (int j = 0; j < 32; j += 8)
        g_wqT[(size_t)(c0+y+j) * 1024 + r0 + x] = __float2bfloat16(t[x][y+j]);
}
__global__ void wtrans_proj(const float* __restrict__ src) {  // [1024][1024]
    __shared__ float t[32][33];
    int c0 = blockIdx.x * 32, r0 = blockIdx.y * 32;
    int x = threadIdx.x, y = threadIdx.y;
    #pragma unroll
    for (int j = 0; j < 32; j += 8)
        t[y+j][x] = src[(size_t)(r0+y+j) * 1024 + c0 + x];
    __syncthreads();
    #pragma unroll
    for (int j = 0; j < 32; j += 8)
        g_wpT[(size_t)(c0+y+j) * 1024 + r0 + x] = __float2bfloat16(t[x][y+j]);
}

// ======================= LayerNorm (bf16 out) ==============================
__global__ void ln_kernel(const float* __restrict__ x,
                          const float* __restrict__ gamma,
                          const float* __restrict__ beta) {
    int row = blockIdx.x;
    int tid = threadIdx.x;
    const float4* xr = reinterpret_cast<const float4*>(x + (size_t)row * D_);
    float4 v = xr[tid];
    float s  = v.x + v.y + v.z + v.w;
    float sq = v.x*v.x + v.y*v.y + v.z*v.z + v.w*v.w;
    #pragma unroll
    for (int o = 16; o > 0; o >>= 1) {
        s  += __shfl_xor_sync(0xffffffffu, s,  o);
        sq += __shfl_xor_sync(0xffffffffu, sq, o);
    }
    __shared__ float ss[8], sq2[8];
    __shared__ float mu_s, rs_s;
    if ((tid & 31) == 0) { ss[tid >> 5] = s; sq2[tid >> 5] = sq; }
    __syncthreads();
    if (tid == 0) {
        float a = 0.f, b2 = 0.f;
        #pragma unroll
        for (int i = 0; i < 8; i++) { a += ss[i]; b2 += sq2[i]; }
        float mu  = a * (1.0f / D_);
        float var = b2 * (1.0f / D_) - mu * mu;
        mu_s = mu;
        rs_s = rsqrtf(var + 1e-5f);
    }
    __syncthreads();
    float mu = mu_s, rs = rs_s;
    float4 g  = reinterpret_cast<const float4*>(gamma)[tid];
    float4 be = reinterpret_cast<const float4*>(beta)[tid];
    float o0 = (v.x - mu) * rs * g.x + be.x;
    float o1 = (v.y - mu) * rs * g.y + be.y;
    float o2 = (v.z - mu) * rs * g.z + be.z;
    float o3 = (v.w - mu) * rs * g.w + be.w;
    uint2 packed = make_uint2(pack_bf16(o0, o1), pack_bf16(o2, o3));
    *reinterpret_cast<uint2*>(g_xnh + (size_t)row * D_ + tid * 4) = packed;
}

// ========= bf16 GEMM core: 256x128 tile, 512 threads, 4-stage ring =========
// A: [M][1024] bf16 row-major. B: [N][1024] bf16 (n-major, k contiguous).
// Stage = A[256 rows x 80B] + B[128 x 80B] = 30720 B; 4 stages = 122880 B.
// 16 warps as 4m x 4n (warp tile 64x32) -- same 16 warps/SM as the old
// 2-CTA config, but B is re-read M/256=32x instead of 64x: L2 traffic -25%.
// Ring logic identical to the proven R14 core (wait_group 2, 1 barrier/iter).
#define GEMM_SMEM 122880

__device__ __forceinline__ void gemm_core_256(
    const bf16* __restrict__ Agm, const bf16* __restrict__ Bgm,
    int m0, int n0, float acc[4][4][4])
{
    extern __shared__ uint32_t smem_u[];
    uint32_t smb = (uint32_t)__cvta_generic_to_shared(smem_u);
    int tid = threadIdx.x, lane = tid & 31, wid = tid >> 5;
    int warp_m = (wid & 3) * 64, warp_n = (wid >> 2) * 32;

    // loaders: A rows 256 (32B/thread), B rows 128 (16B/thread)
    int arow = tid >> 1, ahalf = tid & 1;
    int brow = tid >> 2, bpart = tid & 3;
    const bf16* agp = Agm + (size_t)(m0 + arow) * D_ + ahalf * 16;
    const bf16* bgp = Bgm + (size_t)(n0 + brow) * D_ + bpart * 8;
    uint32_t sa = smb + arow * 80 + ahalf * 32;
    uint32_t sb = smb + 20480 + brow * 80 + bpart * 16;

    // preload stages 0..2 (k-blocks 0..2)
    #pragma unroll
    for (int s = 0; s < 3; s++) {
        cpa16(sa + s * 30720,      agp + s * 32);
        cpa16(sa + s * 30720 + 16, agp + s * 32 + 8);
        cpa16(sb + s * 30720,      bgp + s * 32);
        CP_COMMIT();
    }

    uint32_t a_lane = smb + (warp_m + (lane & 15)) * 80 + ((lane >> 4) << 4);
    uint32_t b_lane = smb + 20480 + (warp_n + (lane & 7)) * 80 +
                      (((lane >> 3) & 1) << 4) + (lane >> 4) * 640;

    #pragma unroll 4
    for (int it = 0; it < 32; it++) {
        if (it < 30)       asm volatile("cp.async.wait_group 2;");
        else if (it == 30) asm volatile("cp.async.wait_group 1;");
        else               asm volatile("cp.async.wait_group 0;");
        __syncthreads();   // stage it%4 visible; stage (it+3)%4 consumers done

        if (it < 29) {     // prefetch k-block it+3 into ring slot (it+3)%4
            uint32_t so = (uint32_t)((it + 3) & 3) * 30720;
            const bf16* ga = agp + (it + 3) * 32;
            const bf16* gb = bgp + (it + 3) * 32;
            cpa16(sa + so,      ga);
            cpa16(sa + so + 16, ga + 8);
            cpa16(sb + so,      gb);
            CP_COMMIT();
        }

        uint32_t ab = a_lane + (it & 3) * 30720;
        uint32_t bb = b_lane + (it & 3) * 30720;
        #pragma unroll
        for (int c = 0; c < 2; c++) {              // 2 chunks of k16
            uint32_t af[4][4], bfr[2][4];
            #pragma unroll
            for (int mt = 0; mt < 4; mt++) ldsm_x4(af[mt], ab + mt * 1280 + c * 32);
            #pragma unroll
            for (int np = 0; np < 2; np++) ldsm_x4(bfr[np], bb + np * 1280 + c * 32);
            #pragma unroll
            for (int mt = 0; mt < 4; mt++)
                #pragma unroll
                for (int np = 0; np < 2; np++) {
                    mma_bf16(acc[mt][2*np],     af[mt], bfr[np]);
                    mma_bf16(acc[mt][2*np + 1], af[mt], bfr[np] + 2);
                }
        }
    }
    __syncthreads();
}

// ======================= QKV GEMM ==========================================
__global__ __launch_bounds__(512, 1) void qkv_gemm(const float* __restrict__ bias) {
    float acc[4][4][4] = {};
    int m0 = blockIdx.y * 256, n0 = blockIdx.x * 128;
    gemm_core_256(g_xnh, g_wqT, m0, n0, acc);

    int lane = threadIdx.x & 31, wid = threadIdx.x >> 5;
    int warp_m = (wid & 3) * 64, warp_n = (wid >> 2) * 32;
    #pragma unroll
    for (int mt = 0; mt < 4; mt++) {
        #pragma unroll
        for (int half = 0; half < 2; half++) {
            int bt = m0 + warp_m + mt * 16 + (lane >> 2) + half * 8;
            int bb = bt >> 11;
            int t  = bt & 2047;
            #pragma unroll
            for (int nt = 0; nt < 4; nt++) {
                int c = n0 + warp_n + nt * 8 + (lane & 3) * 2;
                float v0 = acc[mt][nt][half*2+0] + bias[c];
                float v1 = acc[mt][nt][half*2+1] + bias[c+1];
                int s   = c >> 10;
                int rem = c & 1023;
                int hh  = rem >> 6;
                int d   = rem & 63;
                bf16* dst = (s == 0) ? g_q : ((s == 1) ? g_k : g_v);
                *reinterpret_cast<uint32_t*>(
                    &dst[((size_t)((bb * H_ + hh) * T_) + t) * HD_ + d]) =
                    pack_bf16(v0, v1);
            }
        }
    }
}

// ======================= Proj GEMM + bias + residual =======================
__global__ __launch_bounds__(512, 1) void proj_gemm(const float* __restrict__ bias,
                                                    const float* __restrict__ xres,
                                                    float* __restrict__ out) {
    float acc[4][4][4] = {};
    int m0 = blockIdx.y * 256, n0 = blockIdx.x * 128;
    gemm_core_256(g_aoh, g_wpT, m0, n0, acc);

    int lane = threadIdx.x & 31, wid = threadIdx.x >> 5;
    int warp_m = (wid & 3) * 64, warp_n = (wid >> 2) * 32;
    #pragma unroll
    for (int mt = 0; mt < 4; mt++) {
        #pragma unroll
        for (int half = 0; half < 2; half++) {
            int row = m0 + warp_m + mt * 16 + (lane >> 2) + half * 8;
            #pragma unroll
            for (int nt = 0; nt < 4; nt++) {
                int c = n0 + warp_n + nt * 8 + (lane & 3) * 2;
                float2 bi = *reinterpret_cast<const float2*>(&bias[c]);
                float2 xr = *reinterpret_cast<const float2*>(&xres[(size_t)row * D_ + c]);
                float2 o;
                o.x = acc[mt][nt][half*2+0] + bi.x + xr.x;
                o.y = acc[mt][nt][half*2+1] + bi.y + xr.y;
                *reinterpret_cast<float2*>(&out[(size_t)row * D_ + c]) = o;
            }
        }
    }
}

// ======================= Flash Attention v2 (register softmax) =============
// (unchanged from R16 — passing at rel_err 4.2e-5)
#define ATTN_SMEM 73728

__global__ __launch_bounds__(256, 2) void attn_kernel() {
    extern __shared__ char smraw[];
    uint32_t smem_b = (uint32_t)__cvta_generic_to_shared(smraw);
    const uint32_t K_BASE = 18432, V_BASE = 46080, KV_STG = 9216;

    int tid  = threadIdx.x;
    int lane = tid & 31, wid = tid >> 5;
    int warp_m = wid * 16;
    int g = lane >> 2;

    int qtile = blockIdx.x, h = blockIdx.y, b = blockIdx.z;
    size_t bh = (size_t)(b * H_ + h) * T_ * HD_;
    const bf16* Qg  = g_q + bh + (size_t)qtile * 128 * HD_;
    const bf16* Kg0 = g_k + bh;
    const bf16* Vg0 = g_v + bh;

    int kr = tid >> 2, kp = tid & 3;
    {
        int qr = tid >> 1, qh = tid & 1;
        uint32_t dq = smem_b + qr * 144 + qh * 64;
        const bf16* sq = Qg + qr * 64 + qh * 32;
        cpa16(dq, sq); cpa16(dq + 16, sq + 8);
        cpa16(dq + 32, sq + 16); cpa16(dq + 48, sq + 24);
        uint32_t dk = smem_b + K_BASE + kr * 144 + kp * 32;
        uint32_t dv = smem_b + V_BASE + kr * 144 + kp * 32;
        const bf16* sk = Kg0 + kr * 64 + kp * 16;
        const bf16* sv = Vg0 + kr * 64 + kp * 16;
        cpa16(dk, sk); cpa16(dk + 16, sk + 8);
        cpa16(dv, sv); cpa16(dv + 16, sv + 8);
    }
    CP_COMMIT();
    {
        uint32_t dk = smem_b + K_BASE + KV_STG + kr * 144 + kp * 32;
        uint32_t dv = smem_b + V_BASE + KV_STG + kr * 144 + kp * 32;
        const bf16* sk = Kg0 + (size_t)64 * HD_ + kr * 64 + kp * 16;
        const bf16* sv = Vg0 + (size_t)64 * HD_ + kr * 64 + kp * 16;
        cpa16(dk, sk); cpa16(dk + 16, sk + 8);
        cpa16(dv, sv); cpa16(dv + 16, sv + 8);
    }
    CP_COMMIT();

    uint32_t q_lane = smem_b + (warp_m + (lane & 15)) * 144 + ((lane >> 4) << 4);
    uint32_t k_lane = smem_b + K_BASE + (lane & 7) * 144 +
                      (((lane >> 3) & 1) << 4) + (lane >> 4) * 1152;
    uint32_t v_lane = smem_b + V_BASE + (lane & 15) * 144 + (lane >> 4) * 16;

    float O[8][4] = {};
    float m0r = -1e30f, m1r = -1e30f;
    float l0 = 0.f, l1 = 0.f;

    for (int kt = 0; kt < 32; kt++) {
        if (kt < 31) asm volatile("cp.async.wait_group 1;");
        else         asm volatile("cp.async.wait_group 0;");
        __syncthreads();

        if (kt < 30) {
            uint32_t st = (uint32_t)((kt + 2) % 3) * KV_STG;
            const bf16* sk = Kg0 + (size_t)(kt + 2) * 64 * HD_ + kr * 64 + kp * 16;
            const bf16* sv = Vg0 + (size_t)(kt + 2) * 64 * HD_ + kr * 64 + kp * 16;
            uint32_t dk = smem_b + K_BASE + st + kr * 144 + kp * 32;
            uint32_t dv = smem_b + V_BASE + st + kr * 144 + kp * 32;
            cpa16(dk, sk); cpa16(dk + 16, sk + 8);
            cpa16(dv, sv); cpa16(dv + 16, sv + 8);
            CP_COMMIT();
        }

        uint32_t soff = (uint32_t)(kt % 3) * KV_STG;
        uint32_t kb = k_lane + soff;
        uint32_t vb = v_lane + soff;

        float sacc[8][4] = {};
        #pragma unroll
        for (int c = 0; c < 4; c++) {
            uint32_t qf[4];
            ldsm_x4(qf, q_lane + c * 32);
            #pragma unroll
            for (int np = 0; np < 4; np++) {
                uint32_t kf[4];
                ldsm_x4(kf, kb + np * 2304 + c * 32);
                mma_bf16(sacc[2*np],     qf, kf);
                mma_bf16(sacc[2*np + 1], qf, kf + 2);
            }
        }

        const float scale = 0.125f;
        float mx0 = -1e30f, mx1 = -1e30f;
        #pragma unroll
        for (int nt = 0; nt < 8; nt++) {
            sacc[nt][0] *= scale; sacc[nt][1] *= scale;
            sacc[nt][2] *= scale; sacc[nt][3] *= scale;
            mx0 = fmaxf(mx0, fmaxf(sacc[nt][0], sacc[nt][1]));
            mx1 = fmaxf(mx1, fmaxf(sacc[nt][2], sacc[nt][3]));
        }
        mx0 = fmaxf(mx0, __shfl_xor_sync(0xffffffffu, mx0, 1));
        mx0 = fmaxf(mx0, __shfl_xor_sync(0xffffffffu, mx0, 2));
        mx1 = fmaxf(mx1, __shfl_xor_sync(0xffffffffu, mx1, 1));
        mx1 = fmaxf(mx1, __shfl_xor_sync(0xffffffffu, mx1, 2));
        float mn0 = fmaxf(m0r, mx0), mn1 = fmaxf(m1r, mx1);
        float al0 = __expf(m0r - mn0), al1 = __expf(m1r - mn1);
        float s0 = 0.f, s1 = 0.f;
        uint32_t pf[4][4];
        #pragma unroll
        for (int np = 0; np < 4; np++) {
            float p00 = __expf(sacc[2*np][0]   - mn0), p01 = __expf(sacc[2*np][1]   - mn0);
            float p10 = __expf(sacc[2*np][2]   - mn1), p11 = __expf(sacc[2*np][3]   - mn1);
            float p02 = __expf(sacc[2*np+1][0] - mn0), p03 = __expf(sacc[2*np+1][1] - mn0);
            float p12 = __expf(sacc[2*np+1][2] - mn1), p13 = __expf(sacc[2*np+1][3] - mn1);
            s0 += (p00 + p01) + (p02 + p03);
            s1 += (p10 + p11) + (p12 + p13);
            pf[np][0] = pack_bf16(p00, p01);
            pf[np][1] = pack_bf16(p10, p11);
            pf[np][2] = pack_bf16(p02, p03);
            pf[np][3] = pack_bf16(p12, p13);
        }
        s0 += __shfl_xor_sync(0xffffffffu, s0, 1);
        s0 += __shfl_xor_sync(0xffffffffu, s0, 2);
        s1 += __shfl_xor_sync(0xffffffffu, s1, 1);
        s1 += __shfl_xor_sync(0xffffffffu, s1, 2);
        l0 = l0 * al0 + s0;
        l1 = l1 * al1 + s1;
        m0r = mn0; m1r = mn1;

        #pragma unroll
        for (int nt = 0; nt < 8; nt++) {
            O[nt][0] *= al0; O[nt][1] *= al0;
            O[nt][2] *= al1; O[nt][3] *= al1;
        }
        #pragma unroll
        for (int kc = 0; kc < 4; kc++) {
            #pragma unroll
            for (int np = 0; np < 4; np++) {
                uint32_t vf[4];
                ldsm_x4t(vf, vb + kc * 2304 + np * 32);
                mma_bf16(O[2*np],     pf[kc], vf);
                mma_bf16(O[2*np + 1], pf[kc], vf + 2);
            }
        }
    }

    float li0 = 1.f / l0, li1 = 1.f / l1;
    size_t outbase = ((size_t)b * T_ + qtile * 128 + warp_m) * D_ + h * HD_;
    int t2 = (lane & 3) * 2;
    #pragma unroll
    for (int nt = 0; nt < 8; nt++) {
        int c = nt * 8 + t2;
        *reinterpret_cast<uint32_t*>(&g_aoh[outbase + (size_t)g * D_ + c]) =
            pack_bf16(O[nt][0] * li0, O[nt][1] * li0);
        *reinterpret_cast<uint32_t*>(&g_aoh[outbase + (size_t)(g + 8) * D_ + c]) =
            pack_bf16(O[nt][2] * li1, O[nt][3] * li1);
    }
}

// ======================= launch ============================================
extern "C" void kernel_launch(void* const* d_in, const int* in_sizes, int n_in,
                              void* d_out, int out_size) {
    const float* x      = (const float*)d_in[0];
    const float* w_qkv  = (const float*)d_in[1];
    const float* b_qkv  = (const float*)d_in[2];
    const float* w_proj = (const float*)d_in[3];
    const float* b_proj = (const float*)d_in[4];
    const float* gamma  = (const float*)d_in[5];
    const float* beta   = (const float*)d_in[6];
    float* out = (float*)d_out;

    cudaFuncSetAttribute(attn_kernel,
                         cudaFuncAttributeMaxDynamicSharedMemorySize, ATTN_SMEM);
    cudaFuncSetAttribute(qkv_gemm,
                         cudaFuncAttributeMaxDynamicSharedMemorySize, GEMM_SMEM);
    cudaFuncSetAttribute(proj_gemm,
                         cudaFuncAttributeMaxDynamicSharedMemorySize, GEMM_SMEM);

    wtrans_qkv<<<dim3(96, 32), dim3(32, 8)>>>(w_qkv);
    wtrans_proj<<<dim3(32, 32), dim3(32, 8)>>>(w_proj);
    ln_kernel<<<BT_, 256>>>(x, gamma, beta);
    qkv_gemm<<<dim3(24, 32), 512, GEMM_SMEM>>>(b_qkv);
    attn_kernel<<<dim3(T_ / 128, H_, B_), 256, ATTN_SMEM>>>();
    proj_gemm<<<dim3(8, 32), 512, GEMM_SMEM>>>(b_proj, x, out);
}